// round 11
// baseline (speedup 1.0000x reference)
#include <cuda_runtime.h>
#include <cuda_fp16.h>
#include <cstdint>

// Conv2d 3x3 s1 p1 NCHW fp32: N=32,C=128,H=W=56,OC=256.
// Implicit GEMM mma.sync.m16n8k16 FP16 (fp32 accum). K' = cblk*288 + tap*32 + c.
// R11: (1) conflict-free prep_in transpose read mapping;
//      (2) two taps per barrier window (B loaded in 16KB stage-pairs,
//          3-deep pair ring, wait_group 2) -> half the barriers of R10.

#define N_IMG   32
#define C_IN    128
#define H_DIM   56
#define W_DIM   56
#define OC_DIM  256
#define HW      3136
#define CHW     (C_IN * HW)
#define K_TOTAL 1152
#define M_TOTAL 100352

#define BM 128
#define BN 128
#define THREADS 256
#define NPAIRS 18                        // 36 stages, 2 per iteration

#define NPIX 248                         // 128 m + halo
#define ROWB 80                          // bytes per pixel row (64 data + 16 pad)
#define ABUF_BYTES (NPIX * ROWB)         // 19840
#define B_PAIR_BYTES 16384               // 2 stages x 128 oc x 32 k x 2B
#define A_OFF(i) ((i) * ABUF_BYTES)
#define B_OFF(j) (2 * ABUF_BYTES + (j) * B_PAIR_BYTES)
#define OFF_ZERO (2 * ABUF_BYTES + 3 * B_PAIR_BYTES)      // 88832
#define SMEM_TOTAL (OFF_ZERO + 64)       // 88896

__device__ __align__(16) uint32_t g_in_h2[(size_t)M_TOTAL * 64]; // [pix][cp] fp16x2
__device__ __align__(16) uint32_t g_w_h[OC_DIM * K_TOTAL / 2];   // frag-order fp16x2

__device__ __forceinline__ uint32_t smem_u32(const void* p) {
    uint32_t a;
    asm("{ .reg .u64 t; cvta.to.shared.u64 t, %1; cvt.u32.u64 %0, t; }" : "=r"(a) : "l"(p));
    return a;
}
__device__ __forceinline__ uint32_t pack_h2(float lo, float hi) {
    __half2 h = __halves2half2(__float2half_rn(lo), __float2half_rn(hi));
    return *reinterpret_cast<uint32_t*>(&h);
}
__device__ __forceinline__ void cp16_zfill(uint32_t dst, const void* src, uint32_t sz) {
    asm volatile("cp.async.cg.shared.global [%0], [%1], 16, %2;"
                 :: "r"(dst), "l"(src), "r"(sz) : "memory");
}
__device__ __forceinline__ void cp16(uint32_t dst, const void* src) {
    asm volatile("cp.async.cg.shared.global [%0], [%1], 16;"
                 :: "r"(dst), "l"(src) : "memory");
}
__device__ __forceinline__ void lds128(uint32_t* r, uint32_t addr) {
    asm volatile("ld.shared.v4.u32 {%0,%1,%2,%3}, [%4];"
                 : "=r"(r[0]), "=r"(r[1]), "=r"(r[2]), "=r"(r[3]) : "r"(addr));
}
__device__ __forceinline__ void ldmx4(uint32_t* r, uint32_t addr) {
    asm volatile("ldmatrix.sync.aligned.m8n8.x4.shared.b16 {%0,%1,%2,%3}, [%4];"
                 : "=r"(r[0]), "=r"(r[1]), "=r"(r[2]), "=r"(r[3]) : "r"(addr));
}
__device__ __forceinline__ void mma_f16(float* c, const uint32_t* a,
                                        uint32_t b0, uint32_t b1) {
    asm volatile(
        "mma.sync.aligned.m16n8k16.row.col.f32.f16.f16.f32 "
        "{%0,%1,%2,%3}, {%4,%5,%6,%7}, {%8,%9}, {%0,%1,%2,%3};"
        : "+f"(c[0]), "+f"(c[1]), "+f"(c[2]), "+f"(c[3])
        : "r"(a[0]), "r"(a[1]), "r"(a[2]), "r"(a[3]), "r"(b0), "r"(b1));
}

// ---- prep: input NCHW fp32 -> [pixel][cp] fp16x2 (conflict-free transpose) ----
__global__ void prep_in_kernel(const float* __restrict__ in) {
    __shared__ float sm[128][33];
    const int tid = threadIdx.x;
    const int n   = blockIdx.x / 98;
    const int hw0 = (blockIdx.x - n * 98) * 32;

    // write phase: conflict-free (bank = c + 16*part + j)
    const int c    = tid >> 1;
    const int part = tid & 1;
    const float4* s4 = (const float4*)(in + (size_t)n * CHW + (size_t)c * HW
                                       + hw0 + part * 16);
    #pragma unroll
    for (int e = 0; e < 4; e++) {
        const float4 v = s4[e];
        sm[c][part * 16 + e * 4 + 0] = v.x;
        sm[c][part * 16 + e * 4 + 1] = v.y;
        sm[c][part * 16 + e * 4 + 2] = v.z;
        sm[c][part * 16 + e * 4 + 3] = v.w;
    }
    __syncthreads();

    // read phase: lanes span hw_l = 0..31 -> 32 distinct banks per access
    const int hw_l = tid & 31;
    const int cq   = tid >> 5;
    uint32_t ow[8];
    #pragma unroll
    for (int e = 0; e < 8; e++) {
        const int cp = cq * 8 + e;
        ow[e] = pack_h2(sm[2 * cp][hw_l], sm[2 * cp + 1][hw_l]);
    }
    uint4* dst = (uint4*)(g_in_h2 + (size_t)(n * HW + hw0 + hw_l) * 64 + cq * 8);
    dst[0] = make_uint4(ow[0], ow[1], ow[2], ow[3]);
    dst[1] = make_uint4(ow[4], ow[5], ow[6], ow[7]);
}

// ---- prep: weights -> fp16x2 fragment order ----
// g_w_h layout: [s(36)][half(2)][ks(2)][wn(2)][q(4)][lane(32)][j(4)]
__global__ void prep_w_kernel(const float* __restrict__ wsrc) {
    const int idx  = blockIdx.x * blockDim.x + threadIdx.x;   // [0, 147456)
    const int s    = idx >> 12;
    const int w2   = idx & 4095;
    const int half = w2 >> 11;
    const int w    = w2 & 2047;
    const int ks   = w >> 10;
    const int wn   = (w >> 9) & 1;
    const int q    = (w >> 7) & 3;
    const int lane = (w >> 2) & 31;
    const int j    = w & 3;
    const int grp  = lane >> 2;
    const int tig  = lane & 3;
    const int oc   = half * 128 + wn * 64 + (2 * q + (j >> 1)) * 8 + grp;
    const int c0   = ks * 16 + (j & 1) * 8 + tig * 2;
    const int cblk = s / 9;
    const int rs   = s - 9 * cblk;
    const int ch   = cblk * 32 + c0;
    const float w0 = wsrc[(size_t)oc * K_TOTAL + ch * 9 + rs];
    const float w1 = wsrc[(size_t)oc * K_TOTAL + (ch + 1) * 9 + rs];
    g_w_h[idx] = pack_h2(w0, w1);
}

__global__ void __launch_bounds__(THREADS, 2)
conv2d_mma_kernel(const float* __restrict__ bias, float* __restrict__ out)
{
    extern __shared__ char smem_raw[];
    const uint32_t sbase = smem_u32(smem_raw);
    const uint32_t zaddr = sbase + OFF_ZERO;

    const int tid     = threadIdx.x;
    const int lane    = tid & 31;
    const int wid     = tid >> 5;
    const int m_base  = blockIdx.x * BM;
    const int nh      = blockIdx.y;            // oc half
    const int oc_base = nh * BN;

    if (tid < 16) ((uint32_t*)(smem_raw + OFF_ZERO))[tid] = 0u;

    // ---- A loader: 992 16B chunks (248 pixels x 4) ----
    auto load_A = [&](int cblk) {
        const uint32_t dbase = sbase + A_OFF(cblk & 1);
        #pragma unroll
        for (int j = 0; j < 4; j++) {
            const int ch_i = tid + 256 * j;
            if (ch_i >= NPIX * 4) break;
            const int pix = ch_i >> 2;
            const int t   = ch_i & 3;
            const int g   = m_base - 60 + pix;
            const bool ok = (g >= 0) && (g < M_TOTAL);
            const size_t gc = ok ? (size_t)g : 0;
            cp16_zfill(dbase + (uint32_t)(pix * ROWB + t * 16),
                       g_in_h2 + gc * 64 + cblk * 16 + t * 4,
                       ok ? 16u : 0u);
        }
    };
    // ---- B loader: one 16KB stage-pair (stages 2p, 2p+1) ----
    auto load_Bpair = [&](int p) {
        const uint32_t dst = sbase + B_OFF(p % 3) + (uint32_t)(tid * 16);
        const uint32_t* s0 = g_w_h + (size_t)(2 * p) * 4096 + nh * 2048 + tid * 4;
        cp16(dst,          s0);
        cp16(dst + 4096,   s0 + 1024);
        cp16(dst + 8192,   s0 + 4096);
        cp16(dst + 12288,  s0 + 5120);
    };

    // ---- compute mapping: 4(M) x 2(N) warps, warp tile 32x64 ----
    const int wm  = wid & 3;
    const int wn  = wid >> 2;
    const int grp = lane >> 2;
    const int tig = lane & 3;
    const int l15 = lane & 15;
    const int khalf = lane >> 4;

    int pixloc[2], hh[2], ww[2];
    #pragma unroll
    for (int mi = 0; mi < 2; mi++) {
        const int mrow = wm * 32 + mi * 16 + l15;
        pixloc[mi] = mrow + 60;
        const int m  = m_base + mrow;
        const int nn = m / HW;
        const int hw = m - nn * HW;
        hh[mi] = hw / W_DIM;
        ww[mi] = hw - hh[mi] * W_DIM;
    }

    float acc[2][8][4];
    #pragma unroll
    for (int mi = 0; mi < 2; mi++)
        #pragma unroll
        for (int ni = 0; ni < 8; ni++)
            #pragma unroll
            for (int q = 0; q < 4; q++) acc[mi][ni][q] = 0.0f;

    // ---- prologue: 3 groups (A0+P0 | A1+P1 | P2) ----
    load_A(0); load_Bpair(0);
    asm volatile("cp.async.commit_group;" ::: "memory");
    load_A(1); load_Bpair(1);
    asm volatile("cp.async.commit_group;" ::: "memory");
    load_Bpair(2);
    asm volatile("cp.async.commit_group;" ::: "memory");

    for (int ss = 0; ss < NPAIRS; ss++) {
        asm volatile("cp.async.wait_group 2;" ::: "memory");
        __syncthreads();

        #pragma unroll
        for (int sub = 0; sub < 2; sub++) {
            const int s    = 2 * ss + sub;
            const int cblk = s / 9;
            const int rs   = s - 9 * cblk;
            const int r3   = rs / 3;
            const int dh   = r3 - 1;
            const int dw   = rs - 3 * r3 - 1;

            const uint32_t Ab = sbase + A_OFF(cblk & 1);
            const uint32_t Bb = sbase + B_OFF(ss % 3) + (uint32_t)(sub * 8192);
            const int shift = dh * W_DIM + dw;

            uint32_t ra[2];
            #pragma unroll
            for (int mi = 0; mi < 2; mi++) {
                const bool ok = ((unsigned)(hh[mi] + dh) < (unsigned)H_DIM) &&
                                ((unsigned)(ww[mi] + dw) < (unsigned)W_DIM);
                ra[mi] = ok ? (Ab + (uint32_t)((pixloc[mi] + shift) * ROWB + khalf * 16))
                            : zaddr;
            }

            const uint32_t bb_base = Bb + (uint32_t)(wn * 2048 + lane * 16);
            #pragma unroll
            for (int ks = 0; ks < 2; ks++) {
                uint32_t a[2][4];
                ldmx4(a[0], ra[0] + ks * 32);
                ldmx4(a[1], ra[1] + ks * 32);
                uint32_t bb[4][4];
                #pragma unroll
                for (int q = 0; q < 4; q++)
                    lds128(bb[q], bb_base + (uint32_t)(ks * 4096 + q * 512));
                #pragma unroll
                for (int q = 0; q < 4; q++)
                    #pragma unroll
                    for (int sb = 0; sb < 2; sb++) {
                        const int ni = q * 2 + sb;
                        #pragma unroll
                        for (int mi = 0; mi < 2; mi++)
                            mma_f16(acc[mi][ni], a[mi],
                                    bb[q][sb * 2], bb[q][sb * 2 + 1]);
                    }
            }
        }
        __syncthreads();

        if (ss + 3 < NPAIRS) load_Bpair(ss + 3);
        if (ss == 5) load_A(2);      // buf0 free after iter 4; ready (G8) by iter 9
        if (ss == 9) load_A(3);      // buf1 free after iter 8; ready (G12) by iter 13
        asm volatile("cp.async.commit_group;" ::: "memory");
    }

    // ---- epilogue: +bias, scatter to NCHW ----
    #pragma unroll
    for (int mi = 0; mi < 2; mi++) {
        #pragma unroll
        for (int hf = 0; hf < 2; hf++) {
            const int m   = m_base + wm * 32 + mi * 16 + grp + 8 * hf;
            const int nn  = m / HW;
            const int phw = m - nn * HW;
            float* op = out + (size_t)nn * OC_DIM * HW + phw;
            #pragma unroll
            for (int ni = 0; ni < 8; ni++) {
                const int oc = oc_base + wn * 64 + ni * 8 + 2 * tig;
                const float b0 = __ldg(bias + oc);
                const float b1 = __ldg(bias + oc + 1);
                op[(size_t)oc * HW]       = acc[mi][ni][2 * hf + 0] + b0;
                op[(size_t)(oc + 1) * HW] = acc[mi][ni][2 * hf + 1] + b1;
            }
        }
    }
}

extern "C" void kernel_launch(void* const* d_in, const int* in_sizes, int n_in,
                              void* d_out, int out_size)
{
    const float* in   = (const float*)d_in[0];
    const float* wgt  = (const float*)d_in[1];
    const float* bias = (const float*)d_in[2];
    float* out        = (float*)d_out;

    prep_in_kernel<<<32 * 98, 256>>>(in);
    prep_w_kernel<<<(OC_DIM * K_TOTAL / 2) / 256, 256>>>(wgt);

    cudaFuncSetAttribute(conv2d_mma_kernel,
                         cudaFuncAttributeMaxDynamicSharedMemorySize, SMEM_TOTAL);
    dim3 grid(M_TOTAL / BM, OC_DIM / BN, 1);   // 784 x 2
    conv2d_mma_kernel<<<grid, THREADS, SMEM_TOTAL>>>(bias, out);
}

// round 12
// speedup vs baseline: 1.0356x; 1.0356x over previous
#include <cuda_runtime.h>
#include <cuda_fp16.h>
#include <cstdint>

// Conv2d 3x3 s1 p1 NCHW fp32: N=32,C=128,H=W=56,OC=256.
// Implicit GEMM mma.sync.m16n8k16 FP16 (fp32 accum). K' = cblk*288 + tap*32 + c.
// R12 (base R10): (1) smem-free prep_in direct transpose;
// (2) single __syncthreads per stage with 4-deep B ring (loads in MMA shadow).

#define N_IMG   32
#define C_IN    128
#define H_DIM   56
#define W_DIM   56
#define OC_DIM  256
#define HW      3136
#define CHW     (C_IN * HW)
#define K_TOTAL 1152
#define M_TOTAL 100352

#define BM 128
#define BN 128
#define THREADS 256
#define NSTAGES 36                       // 4 cblk * 9 taps

#define NPIX 248                         // 128 m + halo
#define ROWB 80                          // bytes per pixel row (64 data + 16 pad)
#define ABUF_BYTES (NPIX * ROWB)         // 19840
#define B_STAGE_BYTES 8192               // 128 oc x 32 k x 2B
#define A_OFF(i) ((i) * ABUF_BYTES)
#define B_OFF(j) (2 * ABUF_BYTES + (j) * B_STAGE_BYTES)
#define OFF_ZERO (2 * ABUF_BYTES + 4 * B_STAGE_BYTES)     // 72448
#define SMEM_TOTAL (OFF_ZERO + 64)       // 72512

__device__ __align__(16) uint32_t g_in_h2[(size_t)M_TOTAL * 64]; // [pix][cp] fp16x2
__device__ __align__(16) uint32_t g_w_h[OC_DIM * K_TOTAL / 2];   // frag-order fp16x2

__device__ __forceinline__ uint32_t smem_u32(const void* p) {
    uint32_t a;
    asm("{ .reg .u64 t; cvta.to.shared.u64 t, %1; cvt.u32.u64 %0, t; }" : "=r"(a) : "l"(p));
    return a;
}
__device__ __forceinline__ uint32_t pack_h2(float lo, float hi) {
    __half2 h = __halves2half2(__float2half_rn(lo), __float2half_rn(hi));
    return *reinterpret_cast<uint32_t*>(&h);
}
__device__ __forceinline__ void cp16_zfill(uint32_t dst, const void* src, uint32_t sz) {
    asm volatile("cp.async.cg.shared.global [%0], [%1], 16, %2;"
                 :: "r"(dst), "l"(src), "r"(sz) : "memory");
}
__device__ __forceinline__ void cp16(uint32_t dst, const void* src) {
    asm volatile("cp.async.cg.shared.global [%0], [%1], 16;"
                 :: "r"(dst), "l"(src) : "memory");
}
__device__ __forceinline__ void lds128(uint32_t* r, uint32_t addr) {
    asm volatile("ld.shared.v4.u32 {%0,%1,%2,%3}, [%4];"
                 : "=r"(r[0]), "=r"(r[1]), "=r"(r[2]), "=r"(r[3]) : "r"(addr));
}
__device__ __forceinline__ void ldmx4(uint32_t* r, uint32_t addr) {
    asm volatile("ldmatrix.sync.aligned.m8n8.x4.shared.b16 {%0,%1,%2,%3}, [%4];"
                 : "=r"(r[0]), "=r"(r[1]), "=r"(r[2]), "=r"(r[3]) : "r"(addr));
}
__device__ __forceinline__ void mma_f16(float* c, const uint32_t* a,
                                        uint32_t b0, uint32_t b1) {
    asm volatile(
        "mma.sync.aligned.m16n8k16.row.col.f32.f16.f16.f32 "
        "{%0,%1,%2,%3}, {%4,%5,%6,%7}, {%8,%9}, {%0,%1,%2,%3};"
        : "+f"(c[0]), "+f"(c[1]), "+f"(c[2]), "+f"(c[3])
        : "r"(a[0]), "r"(a[1]), "r"(a[2]), "r"(a[3]), "r"(b0), "r"(b1));
}

// ---- prep: input NCHW fp32 -> [pixel][cp] fp16x2, smem-free direct transpose.
// Thread: 4 consecutive pixels x 16 channels (cq block). Lane-major over pixel
// groups so every LDG.128 is warp-coalesced (32 lanes x 16B contiguous).
__global__ void prep_in_kernel(const float* __restrict__ in) {
    const int idx = blockIdx.x * blockDim.x + threadIdx.x;   // [0, 200704)
    const int cq  = idx / 25088;            // 0..7  (channels 16cq..16cq+15)
    const int r   = idx - cq * 25088;       // n*784 + pg
    const int n   = r / 784;
    const int pg  = r - n * 784;            // pixel group (4 pixels)
    const float* base = in + (size_t)n * CHW + (size_t)(16 * cq) * HW + pg * 4;

    uint32_t w[4][8];                        // [pixel][cp word]
    #pragma unroll
    for (int j = 0; j < 8; j++) {
        const float4 a = *(const float4*)(base + (size_t)(2 * j) * HW);
        const float4 b = *(const float4*)(base + (size_t)(2 * j + 1) * HW);
        w[0][j] = pack_h2(a.x, b.x);
        w[1][j] = pack_h2(a.y, b.y);
        w[2][j] = pack_h2(a.z, b.z);
        w[3][j] = pack_h2(a.w, b.w);
    }
    uint32_t* dst = g_in_h2 + (size_t)(n * HW + pg * 4) * 64 + cq * 8;
    #pragma unroll
    for (int p = 0; p < 4; p++) {
        ((uint4*)(dst + (size_t)p * 64))[0] = make_uint4(w[p][0], w[p][1], w[p][2], w[p][3]);
        ((uint4*)(dst + (size_t)p * 64))[1] = make_uint4(w[p][4], w[p][5], w[p][6], w[p][7]);
    }
}

// ---- prep: weights -> fp16x2 fragment order ----
// g_w_h layout: [s(36)][half(2)][ks(2)][wn(2)][q(4)][lane(32)][j(4)]
__global__ void prep_w_kernel(const float* __restrict__ wsrc) {
    const int idx  = blockIdx.x * blockDim.x + threadIdx.x;   // [0, 147456)
    const int s    = idx >> 12;
    const int w2   = idx & 4095;
    const int half = w2 >> 11;
    const int w    = w2 & 2047;
    const int ks   = w >> 10;
    const int wn   = (w >> 9) & 1;
    const int q    = (w >> 7) & 3;
    const int lane = (w >> 2) & 31;
    const int j    = w & 3;
    const int grp  = lane >> 2;
    const int tig  = lane & 3;
    const int oc   = half * 128 + wn * 64 + (2 * q + (j >> 1)) * 8 + grp;
    const int c0   = ks * 16 + (j & 1) * 8 + tig * 2;
    const int cblk = s / 9;
    const int rs   = s - 9 * cblk;
    const int ch   = cblk * 32 + c0;
    const float w0 = wsrc[(size_t)oc * K_TOTAL + ch * 9 + rs];
    const float w1 = wsrc[(size_t)oc * K_TOTAL + (ch + 1) * 9 + rs];
    g_w_h[idx] = pack_h2(w0, w1);
}

__global__ void __launch_bounds__(THREADS, 2)
conv2d_mma_kernel(const float* __restrict__ bias, float* __restrict__ out)
{
    extern __shared__ char smem_raw[];
    const uint32_t sbase = smem_u32(smem_raw);
    const uint32_t zaddr = sbase + OFF_ZERO;

    const int tid     = threadIdx.x;
    const int lane    = tid & 31;
    const int wid     = tid >> 5;
    const int m_base  = blockIdx.x * BM;
    const int nh      = blockIdx.y;            // oc half
    const int oc_base = nh * BN;

    if (tid < 16) ((uint32_t*)(smem_raw + OFF_ZERO))[tid] = 0u;

    // ---- A loader: 992 16B chunks (248 pixels x 4) ----
    auto load_A = [&](int cblk) {
        const uint32_t dbase = sbase + A_OFF(cblk & 1);
        #pragma unroll
        for (int j = 0; j < 4; j++) {
            const int ch_i = tid + 256 * j;
            if (ch_i >= NPIX * 4) break;
            const int pix = ch_i >> 2;
            const int t   = ch_i & 3;
            const int g   = m_base - 60 + pix;
            const bool ok = (g >= 0) && (g < M_TOTAL);
            const size_t gc = ok ? (size_t)g : 0;
            cp16_zfill(dbase + (uint32_t)(pix * ROWB + t * 16),
                       g_in_h2 + gc * 64 + cblk * 16 + t * 4,
                       ok ? 16u : 0u);
        }
    };
    auto load_B = [&](int s) {
        const uint32_t dst = sbase + B_OFF(s & 3) + (uint32_t)(tid * 16);
        const uint32_t* src = g_w_h + (size_t)s * 4096 + nh * 2048 + tid * 4;
        cp16(dst, src);
        cp16(dst + 4096, src + 1024);
    };

    // ---- compute mapping: 4(M) x 2(N) warps, warp tile 32x64 ----
    const int wm  = wid & 3;
    const int wn  = wid >> 2;
    const int grp = lane >> 2;
    const int tig = lane & 3;
    const int l15 = lane & 15;
    const int khalf = lane >> 4;

    int pixloc[2], hh[2], ww[2];
    #pragma unroll
    for (int mi = 0; mi < 2; mi++) {
        const int mrow = wm * 32 + mi * 16 + l15;
        pixloc[mi] = mrow + 60;
        const int m  = m_base + mrow;
        const int nn = m / HW;
        const int hw = m - nn * HW;
        hh[mi] = hw / W_DIM;
        ww[mi] = hw - hh[mi] * W_DIM;
    }

    float acc[2][8][4];
    #pragma unroll
    for (int mi = 0; mi < 2; mi++)
        #pragma unroll
        for (int ni = 0; ni < 8; ni++)
            #pragma unroll
            for (int q = 0; q < 4; q++) acc[mi][ni][q] = 0.0f;

    load_A(0); load_B(0);
    asm volatile("cp.async.commit_group;" ::: "memory");
    load_A(1); load_B(1);
    asm volatile("cp.async.commit_group;" ::: "memory");
    load_B(2);
    asm volatile("cp.async.commit_group;" ::: "memory");

    int tap = 0, cblk = 0, dh = -1, dw = -1;
    for (int s = 0; s < NSTAGES; s++) {
        asm volatile("cp.async.wait_group 2;" ::: "memory");
        __syncthreads();

        // issue next loads into the MMA shadow (buffers last read at s-1,
        // protected by the sync above)
        if (s + 3 < NSTAGES) load_B(s + 3);
        if (tap == 0 && cblk < 3) load_A(cblk + 1);
        asm volatile("cp.async.commit_group;" ::: "memory");

        const uint32_t Ab = sbase + A_OFF(cblk & 1);
        const uint32_t Bb = sbase + B_OFF(s & 3);
        const int shift = dh * W_DIM + dw;

        uint32_t ra[2];
        #pragma unroll
        for (int mi = 0; mi < 2; mi++) {
            const bool ok = ((unsigned)(hh[mi] + dh) < (unsigned)H_DIM) &&
                            ((unsigned)(ww[mi] + dw) < (unsigned)W_DIM);
            ra[mi] = ok ? (Ab + (uint32_t)((pixloc[mi] + shift) * ROWB + khalf * 16))
                        : zaddr;
        }

        const uint32_t bb_base = Bb + (uint32_t)(wn * 2048 + lane * 16);
        #pragma unroll
        for (int ks = 0; ks < 2; ks++) {
            uint32_t a[2][4];
            ldmx4(a[0], ra[0] + ks * 32);
            ldmx4(a[1], ra[1] + ks * 32);
            uint32_t bb[4][4];
            #pragma unroll
            for (int q = 0; q < 4; q++)
                lds128(bb[q], bb_base + (uint32_t)(ks * 4096 + q * 512));
            #pragma unroll
            for (int q = 0; q < 4; q++)
                #pragma unroll
                for (int sb = 0; sb < 2; sb++) {
                    const int ni = q * 2 + sb;
                    #pragma unroll
                    for (int mi = 0; mi < 2; mi++)
                        mma_f16(acc[mi][ni], a[mi],
                                bb[q][sb * 2], bb[q][sb * 2 + 1]);
                }
        }

        if (++tap == 9) { tap = 0; cblk++; dh = -1; dw = -1; }
        else { if (++dw == 2) { dw = -1; dh++; } }
    }

    // ---- epilogue: +bias, scatter to NCHW ----
    #pragma unroll
    for (int mi = 0; mi < 2; mi++) {
        #pragma unroll
        for (int hf = 0; hf < 2; hf++) {
            const int m   = m_base + wm * 32 + mi * 16 + grp + 8 * hf;
            const int nn  = m / HW;
            const int phw = m - nn * HW;
            float* op = out + (size_t)nn * OC_DIM * HW + phw;
            #pragma unroll
            for (int ni = 0; ni < 8; ni++) {
                const int oc = oc_base + wn * 64 + ni * 8 + 2 * tig;
                const float b0 = __ldg(bias + oc);
                const float b1 = __ldg(bias + oc + 1);
                op[(size_t)oc * HW]       = acc[mi][ni][2 * hf + 0] + b0;
                op[(size_t)(oc + 1) * HW] = acc[mi][ni][2 * hf + 1] + b1;
            }
        }
    }
}

extern "C" void kernel_launch(void* const* d_in, const int* in_sizes, int n_in,
                              void* d_out, int out_size)
{
    const float* in   = (const float*)d_in[0];
    const float* wgt  = (const float*)d_in[1];
    const float* bias = (const float*)d_in[2];
    float* out        = (float*)d_out;

    prep_in_kernel<<<200704 / 256, 256>>>(in);
    prep_w_kernel<<<(OC_DIM * K_TOTAL / 2) / 256, 256>>>(wgt);

    cudaFuncSetAttribute(conv2d_mma_kernel,
                         cudaFuncAttributeMaxDynamicSharedMemorySize, SMEM_TOTAL);
    dim3 grid(M_TOTAL / BM, OC_DIM / BN, 1);   // 784 x 2
    conv2d_mma_kernel<<<grid, THREADS, SMEM_TOTAL>>>(bias, out);
}

// round 13
// speedup vs baseline: 1.0384x; 1.0027x over previous
#include <cuda_runtime.h>
#include <cuda_fp16.h>
#include <cstdint>

// Conv2d 3x3 s1 p1 NCHW fp32: N=32,C=128,H=W=56,OC=256.
// Implicit GEMM mma.sync.m16n8k16 FP16 (fp32 accum). K' = cblk*288 + tap*32 + c.
// R13: prep_in v3 (64-pix smem transpose, vector STS/LDG, MLP=8);
// main loop = R12 single-sync + A-block loads split across taps 0/1.

#define N_IMG   32
#define C_IN    128
#define H_DIM   56
#define W_DIM   56
#define OC_DIM  256
#define HW      3136
#define CHW     (C_IN * HW)
#define K_TOTAL 1152
#define M_TOTAL 100352

#define BM 128
#define BN 128
#define THREADS 256
#define NSTAGES 36                       // 4 cblk * 9 taps

#define NPIX 248                         // 128 m + halo
#define ROWB 80                          // bytes per pixel row (64 data + 16 pad)
#define ABUF_BYTES (NPIX * ROWB)         // 19840
#define B_STAGE_BYTES 8192               // 128 oc x 32 k x 2B
#define A_OFF(i) ((i) * ABUF_BYTES)
#define B_OFF(j) (2 * ABUF_BYTES + (j) * B_STAGE_BYTES)
#define OFF_ZERO (2 * ABUF_BYTES + 4 * B_STAGE_BYTES)     // 72448
#define SMEM_TOTAL (OFF_ZERO + 64)       // 72512

__device__ __align__(16) uint32_t g_in_h2[(size_t)M_TOTAL * 64]; // [pix][cp] fp16x2
__device__ __align__(16) uint32_t g_w_h[OC_DIM * K_TOTAL / 2];   // frag-order fp16x2

__device__ __forceinline__ uint32_t smem_u32(const void* p) {
    uint32_t a;
    asm("{ .reg .u64 t; cvta.to.shared.u64 t, %1; cvt.u32.u64 %0, t; }" : "=r"(a) : "l"(p));
    return a;
}
__device__ __forceinline__ uint32_t pack_h2(float lo, float hi) {
    __half2 h = __halves2half2(__float2half_rn(lo), __float2half_rn(hi));
    return *reinterpret_cast<uint32_t*>(&h);
}
__device__ __forceinline__ void cp16_zfill(uint32_t dst, const void* src, uint32_t sz) {
    asm volatile("cp.async.cg.shared.global [%0], [%1], 16, %2;"
                 :: "r"(dst), "l"(src), "r"(sz) : "memory");
}
__device__ __forceinline__ void cp16(uint32_t dst, const void* src) {
    asm volatile("cp.async.cg.shared.global [%0], [%1], 16;"
                 :: "r"(dst), "l"(src) : "memory");
}
__device__ __forceinline__ void lds128(uint32_t* r, uint32_t addr) {
    asm volatile("ld.shared.v4.u32 {%0,%1,%2,%3}, [%4];"
                 : "=r"(r[0]), "=r"(r[1]), "=r"(r[2]), "=r"(r[3]) : "r"(addr));
}
__device__ __forceinline__ void ldmx4(uint32_t* r, uint32_t addr) {
    asm volatile("ldmatrix.sync.aligned.m8n8.x4.shared.b16 {%0,%1,%2,%3}, [%4];"
                 : "=r"(r[0]), "=r"(r[1]), "=r"(r[2]), "=r"(r[3]) : "r"(addr));
}
__device__ __forceinline__ void mma_f16(float* c, const uint32_t* a,
                                        uint32_t b0, uint32_t b1) {
    asm volatile(
        "mma.sync.aligned.m16n8k16.row.col.f32.f16.f16.f32 "
        "{%0,%1,%2,%3}, {%4,%5,%6,%7}, {%8,%9}, {%0,%1,%2,%3};"
        : "+f"(c[0]), "+f"(c[1]), "+f"(c[2]), "+f"(c[3])
        : "r"(a[0]), "r"(a[1]), "r"(a[2]), "r"(a[3]), "r"(b0), "r"(b1));
}

// ---- prep v3: input NCHW fp32 -> [pixel][cp] fp16x2.
// 64-pixel x 128-channel tile per block; phase1 8x coalesced LDG.128->STS.128
// (MLP=8), phase2 conflict-free LDS.32 + sector-complete STG.128.
__global__ void prep_in_kernel(const float* __restrict__ in) {
    __shared__ float sm[128][68];         // row stride 272B (16B-aligned, odd*16)
    const int tid = threadIdx.x;
    const int n   = blockIdx.x / 49;
    const int hw0 = (blockIdx.x - n * 49) * 64;

    const float* src = in + (size_t)n * CHW + hw0;
    #pragma unroll
    for (int i = 0; i < 8; i++) {
        const int idx = tid + 256 * i;    // [0, 2048)
        const int c   = idx >> 4;
        const int f   = idx & 15;
        const float4 v = *(const float4*)(src + (size_t)c * HW + 4 * f);
        *(float4*)&sm[c][4 * f] = v;
    }
    __syncthreads();

    const int p = tid & 63;               // pixel within tile
    const int q = tid >> 6;               // cp block (16 words)
    uint32_t w[16];
    #pragma unroll
    for (int e = 0; e < 16; e++) {
        const int cp = q * 16 + e;
        w[e] = pack_h2(sm[2 * cp][p], sm[2 * cp + 1][p]);
    }
    uint4* dst = (uint4*)(g_in_h2 + (size_t)(n * HW + hw0 + p) * 64 + q * 16);
    dst[0] = make_uint4(w[0],  w[1],  w[2],  w[3]);
    dst[1] = make_uint4(w[4],  w[5],  w[6],  w[7]);
    dst[2] = make_uint4(w[8],  w[9],  w[10], w[11]);
    dst[3] = make_uint4(w[12], w[13], w[14], w[15]);
}

// ---- prep: weights -> fp16x2 fragment order ----
// g_w_h layout: [s(36)][half(2)][ks(2)][wn(2)][q(4)][lane(32)][j(4)]
__global__ void prep_w_kernel(const float* __restrict__ wsrc) {
    const int idx  = blockIdx.x * blockDim.x + threadIdx.x;   // [0, 147456)
    const int s    = idx >> 12;
    const int w2   = idx & 4095;
    const int half = w2 >> 11;
    const int w    = w2 & 2047;
    const int ks   = w >> 10;
    const int wn   = (w >> 9) & 1;
    const int q    = (w >> 7) & 3;
    const int lane = (w >> 2) & 31;
    const int j    = w & 3;
    const int grp  = lane >> 2;
    const int tig  = lane & 3;
    const int oc   = half * 128 + wn * 64 + (2 * q + (j >> 1)) * 8 + grp;
    const int c0   = ks * 16 + (j & 1) * 8 + tig * 2;
    const int cblk = s / 9;
    const int rs   = s - 9 * cblk;
    const int ch   = cblk * 32 + c0;
    const float w0 = wsrc[(size_t)oc * K_TOTAL + ch * 9 + rs];
    const float w1 = wsrc[(size_t)oc * K_TOTAL + (ch + 1) * 9 + rs];
    g_w_h[idx] = pack_h2(w0, w1);
}

__global__ void __launch_bounds__(THREADS, 2)
conv2d_mma_kernel(const float* __restrict__ bias, float* __restrict__ out)
{
    extern __shared__ char smem_raw[];
    const uint32_t sbase = smem_u32(smem_raw);
    const uint32_t zaddr = sbase + OFF_ZERO;

    const int tid     = threadIdx.x;
    const int lane    = tid & 31;
    const int wid     = tid >> 5;
    const int m_base  = blockIdx.x * BM;
    const int nh      = blockIdx.y;            // oc half
    const int oc_base = nh * BN;

    if (tid < 16) ((uint32_t*)(smem_raw + OFF_ZERO))[tid] = 0u;

    // ---- A loader: 992 16B chunks; part 0 -> chunks [0,512), part 1 -> rest ----
    auto load_A_part = [&](int cblk, int part) {
        const uint32_t dbase = sbase + A_OFF(cblk & 1);
        #pragma unroll
        for (int j = 0; j < 2; j++) {
            const int ch_i = tid + 256 * (2 * part + j);
            if (ch_i >= NPIX * 4) break;
            const int pix = ch_i >> 2;
            const int t   = ch_i & 3;
            const int g   = m_base - 60 + pix;
            const bool ok = (g >= 0) && (g < M_TOTAL);
            const size_t gc = ok ? (size_t)g : 0;
            cp16_zfill(dbase + (uint32_t)(pix * ROWB + t * 16),
                       g_in_h2 + gc * 64 + cblk * 16 + t * 4,
                       ok ? 16u : 0u);
        }
    };
    auto load_B = [&](int s) {
        const uint32_t dst = sbase + B_OFF(s & 3) + (uint32_t)(tid * 16);
        const uint32_t* src = g_w_h + (size_t)s * 4096 + nh * 2048 + tid * 4;
        cp16(dst, src);
        cp16(dst + 4096, src + 1024);
    };

    // ---- compute mapping: 4(M) x 2(N) warps, warp tile 32x64 ----
    const int wm  = wid & 3;
    const int wn  = wid >> 2;
    const int grp = lane >> 2;
    const int tig = lane & 3;
    const int l15 = lane & 15;
    const int khalf = lane >> 4;

    int pixloc[2], hh[2], ww[2];
    #pragma unroll
    for (int mi = 0; mi < 2; mi++) {
        const int mrow = wm * 32 + mi * 16 + l15;
        pixloc[mi] = mrow + 60;
        const int m  = m_base + mrow;
        const int nn = m / HW;
        const int hw = m - nn * HW;
        hh[mi] = hw / W_DIM;
        ww[mi] = hw - hh[mi] * W_DIM;
    }

    float acc[2][8][4];
    #pragma unroll
    for (int mi = 0; mi < 2; mi++)
        #pragma unroll
        for (int ni = 0; ni < 8; ni++)
            #pragma unroll
            for (int q = 0; q < 4; q++) acc[mi][ni][q] = 0.0f;

    load_A_part(0, 0); load_A_part(0, 1); load_B(0);
    asm volatile("cp.async.commit_group;" ::: "memory");
    load_A_part(1, 0); load_A_part(1, 1); load_B(1);
    asm volatile("cp.async.commit_group;" ::: "memory");
    load_B(2);
    asm volatile("cp.async.commit_group;" ::: "memory");

    int tap = 0, cblk = 0, dh = -1, dw = -1;
    for (int s = 0; s < NSTAGES; s++) {
        asm volatile("cp.async.wait_group 2;" ::: "memory");
        __syncthreads();

        // issue next loads into the MMA shadow (buffers last read at s-1)
        if (s + 3 < NSTAGES) load_B(s + 3);
        if (tap == 0 && cblk < 3) load_A_part(cblk + 1, 0);
        if (tap == 1 && cblk < 3) load_A_part(cblk + 1, 1);
        asm volatile("cp.async.commit_group;" ::: "memory");

        const uint32_t Ab = sbase + A_OFF(cblk & 1);
        const uint32_t Bb = sbase + B_OFF(s & 3);
        const int shift = dh * W_DIM + dw;

        uint32_t ra[2];
        #pragma unroll
        for (int mi = 0; mi < 2; mi++) {
            const bool ok = ((unsigned)(hh[mi] + dh) < (unsigned)H_DIM) &&
                            ((unsigned)(ww[mi] + dw) < (unsigned)W_DIM);
            ra[mi] = ok ? (Ab + (uint32_t)((pixloc[mi] + shift) * ROWB + khalf * 16))
                        : zaddr;
        }

        const uint32_t bb_base = Bb + (uint32_t)(wn * 2048 + lane * 16);
        #pragma unroll
        for (int ks = 0; ks < 2; ks++) {
            uint32_t a[2][4];
            ldmx4(a[0], ra[0] + ks * 32);
            ldmx4(a[1], ra[1] + ks * 32);
            uint32_t bb[4][4];
            #pragma unroll
            for (int q = 0; q < 4; q++)
                lds128(bb[q], bb_base + (uint32_t)(ks * 4096 + q * 512));
            #pragma unroll
            for (int q = 0; q < 4; q++)
                #pragma unroll
                for (int sb = 0; sb < 2; sb++) {
                    const int ni = q * 2 + sb;
                    #pragma unroll
                    for (int mi = 0; mi < 2; mi++)
                        mma_f16(acc[mi][ni], a[mi],
                                bb[q][sb * 2], bb[q][sb * 2 + 1]);
                }
        }

        if (++tap == 9) { tap = 0; cblk++; dh = -1; dw = -1; }
        else { if (++dw == 2) { dw = -1; dh++; } }
    }

    // ---- epilogue: +bias, scatter to NCHW ----
    #pragma unroll
    for (int mi = 0; mi < 2; mi++) {
        #pragma unroll
        for (int hf = 0; hf < 2; hf++) {
            const int m   = m_base + wm * 32 + mi * 16 + grp + 8 * hf;
            const int nn  = m / HW;
            const int phw = m - nn * HW;
            float* op = out + (size_t)nn * OC_DIM * HW + phw;
            #pragma unroll
            for (int ni = 0; ni < 8; ni++) {
                const int oc = oc_base + wn * 64 + ni * 8 + 2 * tig;
                const float b0 = __ldg(bias + oc);
                const float b1 = __ldg(bias + oc + 1);
                op[(size_t)oc * HW]       = acc[mi][ni][2 * hf + 0] + b0;
                op[(size_t)(oc + 1) * HW] = acc[mi][ni][2 * hf + 1] + b1;
            }
        }
    }
}

extern "C" void kernel_launch(void* const* d_in, const int* in_sizes, int n_in,
                              void* d_out, int out_size)
{
    const float* in   = (const float*)d_in[0];
    const float* wgt  = (const float*)d_in[1];
    const float* bias = (const float*)d_in[2];
    float* out        = (float*)d_out;

    prep_in_kernel<<<32 * 49, 256>>>(in);
    prep_w_kernel<<<(OC_DIM * K_TOTAL / 2) / 256, 256>>>(wgt);

    cudaFuncSetAttribute(conv2d_mma_kernel,
                         cudaFuncAttributeMaxDynamicSharedMemorySize, SMEM_TOTAL);
    dim3 grid(M_TOTAL / BM, OC_DIM / BN, 1);   // 784 x 2
    conv2d_mma_kernel<<<grid, THREADS, SMEM_TOTAL>>>(bias, out);
}